// round 1
// baseline (speedup 1.0000x reference)
#include <cuda_runtime.h>
#include <math.h>

#define BATCH 4
#define SEQ   2048
#define DIM   1024
#define HEADS 16
#define DH    64
#define MTOT  (BATCH*SEQ)      // 8192
#define QKVN  (3*DIM)          // 3072

// Scratch (device globals: allocation-free per harness rules)
__device__ float g_Q[BATCH*HEADS*SEQ*DH];  // [b,h,n,d]
__device__ float g_K[BATCH*HEADS*SEQ*DH];
__device__ float g_V[BATCH*HEADS*SEQ*DH];
__device__ float g_O[BATCH*SEQ*DIM];       // [b,n,h*d]

// ---------------------------------------------------------------------------
// Kernel 1: QKV GEMM. C[M=8192, N=3072] = x @ w_qkv, scattered into g_Q/K/V.
// 128x128 tile, BK=8, 256 threads, 8x8 per thread.
// ---------------------------------------------------------------------------
__global__ __launch_bounds__(256) void qkv_gemm(const float* __restrict__ x,
                                                const float* __restrict__ w) {
    __shared__ float As[8*128];   // [k][m]
    __shared__ float Bs[8*128];   // [k][n]
    const int tid = threadIdx.x;
    const int tx = tid & 15, ty = tid >> 4;
    const int bm = blockIdx.x * 128;
    const int bn = blockIdx.y * 128;

    const int a_row = tid >> 1, a_col = (tid & 1) * 4;   // A: 128 rows x 8 cols
    const int b_row = tid >> 5, b_col = (tid & 31) * 4;  // B: 8 rows x 128 cols

    float acc[8][8];
#pragma unroll
    for (int i = 0; i < 8; ++i)
#pragma unroll
        for (int j = 0; j < 8; ++j) acc[i][j] = 0.f;

    for (int k0 = 0; k0 < DIM; k0 += 8) {
        float4 av = *(const float4*)&x[(size_t)(bm + a_row) * DIM + k0 + a_col];
        float4 bv = *(const float4*)&w[(size_t)(k0 + b_row) * QKVN + bn + b_col];
        As[(a_col + 0) * 128 + a_row] = av.x;
        As[(a_col + 1) * 128 + a_row] = av.y;
        As[(a_col + 2) * 128 + a_row] = av.z;
        As[(a_col + 3) * 128 + a_row] = av.w;
        *(float4*)&Bs[b_row * 128 + b_col] = bv;
        __syncthreads();
#pragma unroll
        for (int k = 0; k < 8; ++k) {
            float a[8], b[8];
            *(float4*)&a[0] = *(const float4*)&As[k * 128 + ty * 8];
            *(float4*)&a[4] = *(const float4*)&As[k * 128 + ty * 8 + 4];
            *(float4*)&b[0] = *(const float4*)&Bs[k * 128 + tx * 8];
            *(float4*)&b[4] = *(const float4*)&Bs[k * 128 + tx * 8 + 4];
#pragma unroll
            for (int i = 0; i < 8; ++i)
#pragma unroll
                for (int j = 0; j < 8; ++j) acc[i][j] = fmaf(a[i], b[j], acc[i][j]);
        }
        __syncthreads();
    }

    // Scatter epilogue into [b,h,n,d]. A 128-wide tile stays in one section.
    const int sec = bn / DIM;                // 0=Q 1=K 2=V
    float* Gp = (sec == 0) ? g_Q : (sec == 1 ? g_K : g_V);
    const int inner_base = (bn - sec * DIM) + tx * 8;   // multiple of 8
    const int h = inner_base >> 6;
    const int d = inner_base & 63;
#pragma unroll
    for (int i = 0; i < 8; ++i) {
        int r = bm + ty * 8 + i;
        int bb = r >> 11, nn = r & (SEQ - 1);
        float* dst = Gp + (((size_t)(bb * HEADS + h) * SEQ + nn) * DH + d);
        *(float4*)dst = make_float4(acc[i][0], acc[i][1], acc[i][2], acc[i][3]);
        *(float4*)(dst + 4) = make_float4(acc[i][4], acc[i][5], acc[i][6], acc[i][7]);
    }
}

// ---------------------------------------------------------------------------
// Kernel 2: flash attention, fp32. 64x64 tiles, 256 threads (16x16, 4x4 each).
// SMEM: Qs[64][68] (row=q,col=k-dim), Kt[64][68] (row=k-dim,col=key; reused as
// Ps[qrow][key]), Vs[64][68] (row=key,col=d).
// ---------------------------------------------------------------------------
#define SROW 68
#define SMEM_ATTN (3 * 64 * SROW * 4)

__global__ __launch_bounds__(256) void flash_attn() {
    extern __shared__ float sm[];
    float* Qs = sm;
    float* Kt = sm + 64 * SROW;   // reused as Ps after S compute
    float* Vs = sm + 2 * 64 * SROW;

    const int tid = threadIdx.x;
    const int tx = tid & 15, ty = tid >> 4;
    const int ty4 = ty * 4, tx4 = tx * 4;
    const int bh = blockIdx.y;                 // b*HEADS + h
    const int q0 = blockIdx.x * 64;
    const float* Qg = g_Q + (size_t)bh * SEQ * DH;
    const float* Kg = g_K + (size_t)bh * SEQ * DH;
    const float* Vg = g_V + (size_t)bh * SEQ * DH;
    const float scale = 0.125f;   // 1/sqrt(64)

    // Load Q tile (pre-scaled)
#pragma unroll
    for (int it = 0; it < 4; ++it) {
        int i = tid + it * 256;                 // float4 id, 0..1023
        int r = i >> 4, c4 = (i & 15) << 2;
        float4 v = *(const float4*)&Qg[(size_t)(q0 + r) * DH + c4];
        float4 sv = make_float4(v.x * scale, v.y * scale, v.z * scale, v.w * scale);
        *(float4*)&Qs[r * SROW + c4] = sv;
    }
    __syncthreads();

    float m[4], l[4], o[4][4];
#pragma unroll
    for (int i = 0; i < 4; ++i) {
        m[i] = -1e30f; l[i] = 0.f;
#pragma unroll
        for (int j = 0; j < 4; ++j) o[i][j] = 0.f;
    }

    for (int kv0 = 0; kv0 < SEQ; kv0 += 64) {
        __syncthreads();   // previous PV done before overwriting Kt/Vs
        // Load K (transposed into Kt) and V
#pragma unroll
        for (int it = 0; it < 4; ++it) {
            int i = tid + it * 256;
            int r = i >> 4, c4 = (i & 15) << 2;
            float4 kv = *(const float4*)&Kg[(size_t)(kv0 + r) * DH + c4];
            Kt[(c4 + 0) * SROW + r] = kv.x;
            Kt[(c4 + 1) * SROW + r] = kv.y;
            Kt[(c4 + 2) * SROW + r] = kv.z;
            Kt[(c4 + 3) * SROW + r] = kv.w;
            float4 vv = *(const float4*)&Vg[(size_t)(kv0 + r) * DH + c4];
            *(float4*)&Vs[r * SROW + c4] = vv;
        }
        __syncthreads();

        // S = Q K^T (scaled)
        float s[4][4];
#pragma unroll
        for (int i = 0; i < 4; ++i)
#pragma unroll
            for (int j = 0; j < 4; ++j) s[i][j] = 0.f;
#pragma unroll
        for (int kk = 0; kk < 64; kk += 4) {
            float qa[4][4], kb[4][4];
#pragma unroll
            for (int i = 0; i < 4; ++i)
                *(float4*)&qa[i][0] = *(const float4*)&Qs[(ty4 + i) * SROW + kk];
#pragma unroll
            for (int t = 0; t < 4; ++t)
                *(float4*)&kb[t][0] = *(const float4*)&Kt[(kk + t) * SROW + tx4];
#pragma unroll
            for (int i = 0; i < 4; ++i)
#pragma unroll
                for (int j = 0; j < 4; ++j) {
                    s[i][j] = fmaf(qa[i][0], kb[0][j], s[i][j]);
                    s[i][j] = fmaf(qa[i][1], kb[1][j], s[i][j]);
                    s[i][j] = fmaf(qa[i][2], kb[2][j], s[i][j]);
                    s[i][j] = fmaf(qa[i][3], kb[3][j], s[i][j]);
                }
        }
        __syncthreads();   // all threads done reading Kt before Ps overwrite

        // Online softmax (row reductions over tx via shfl)
#pragma unroll
        for (int i = 0; i < 4; ++i) {
            float mx = fmaxf(fmaxf(s[i][0], s[i][1]), fmaxf(s[i][2], s[i][3]));
#pragma unroll
            for (int off = 1; off < 16; off <<= 1)
                mx = fmaxf(mx, __shfl_xor_sync(0xffffffffu, mx, off));
            float mn = fmaxf(m[i], mx);
            float sum = 0.f;
#pragma unroll
            for (int j = 0; j < 4; ++j) {
                float p = __expf(s[i][j] - mn);
                s[i][j] = p;
                sum += p;
            }
#pragma unroll
            for (int off = 1; off < 16; off <<= 1)
                sum += __shfl_xor_sync(0xffffffffu, sum, off);
            float alpha = __expf(m[i] - mn);
            l[i] = l[i] * alpha + sum;
            m[i] = mn;
#pragma unroll
            for (int j = 0; j < 4; ++j) o[i][j] *= alpha;
        }

        // Write P into Kt buffer (Ps[qrow][key])
#pragma unroll
        for (int i = 0; i < 4; ++i)
            *(float4*)&Kt[(ty4 + i) * SROW + tx4] =
                make_float4(s[i][0], s[i][1], s[i][2], s[i][3]);
        __syncthreads();

        // O += P V
#pragma unroll
        for (int kk = 0; kk < 64; kk += 4) {
            float pa[4][4], vb[4][4];
#pragma unroll
            for (int i = 0; i < 4; ++i)
                *(float4*)&pa[i][0] = *(const float4*)&Kt[(ty4 + i) * SROW + kk];
#pragma unroll
            for (int t = 0; t < 4; ++t)
                *(float4*)&vb[t][0] = *(const float4*)&Vs[(kk + t) * SROW + tx4];
#pragma unroll
            for (int i = 0; i < 4; ++i)
#pragma unroll
                for (int j = 0; j < 4; ++j) {
                    o[i][j] = fmaf(pa[i][0], vb[0][j], o[i][j]);
                    o[i][j] = fmaf(pa[i][1], vb[1][j], o[i][j]);
                    o[i][j] = fmaf(pa[i][2], vb[2][j], o[i][j]);
                    o[i][j] = fmaf(pa[i][3], vb[3][j], o[i][j]);
                }
        }
    }

    // Epilogue: normalize and write to g_O in [b, n, h*d]
    const int bb = bh >> 4, hh = bh & 15;
#pragma unroll
    for (int i = 0; i < 4; ++i) {
        float inv = 1.f / l[i];
        int n = q0 + ty4 + i;
        float* dst = g_O + ((size_t)(bb * SEQ + n) * DIM + hh * DH + tx4);
        *(float4*)dst = make_float4(o[i][0] * inv, o[i][1] * inv,
                                    o[i][2] * inv, o[i][3] * inv);
    }
}

// ---------------------------------------------------------------------------
// Kernel 3: output projection. out[8192,1024] = g_O @ w_out + b_out
// ---------------------------------------------------------------------------
__global__ __launch_bounds__(256) void out_gemm(const float* __restrict__ w,
                                                const float* __restrict__ bias,
                                                float* __restrict__ out) {
    __shared__ float As[8*128];
    __shared__ float Bs[8*128];
    const int tid = threadIdx.x;
    const int tx = tid & 15, ty = tid >> 4;
    const int bm = blockIdx.x * 128;
    const int bn = blockIdx.y * 128;

    const int a_row = tid >> 1, a_col = (tid & 1) * 4;
    const int b_row = tid >> 5, b_col = (tid & 31) * 4;

    float acc[8][8];
#pragma unroll
    for (int i = 0; i < 8; ++i)
#pragma unroll
        for (int j = 0; j < 8; ++j) acc[i][j] = 0.f;

    for (int k0 = 0; k0 < DIM; k0 += 8) {
        float4 av = *(const float4*)&g_O[(size_t)(bm + a_row) * DIM + k0 + a_col];
        float4 bv = *(const float4*)&w[(size_t)(k0 + b_row) * DIM + bn + b_col];
        As[(a_col + 0) * 128 + a_row] = av.x;
        As[(a_col + 1) * 128 + a_row] = av.y;
        As[(a_col + 2) * 128 + a_row] = av.z;
        As[(a_col + 3) * 128 + a_row] = av.w;
        *(float4*)&Bs[b_row * 128 + b_col] = bv;
        __syncthreads();
#pragma unroll
        for (int k = 0; k < 8; ++k) {
            float a[8], b[8];
            *(float4*)&a[0] = *(const float4*)&As[k * 128 + ty * 8];
            *(float4*)&a[4] = *(const float4*)&As[k * 128 + ty * 8 + 4];
            *(float4*)&b[0] = *(const float4*)&Bs[k * 128 + tx * 8];
            *(float4*)&b[4] = *(const float4*)&Bs[k * 128 + tx * 8 + 4];
#pragma unroll
            for (int i = 0; i < 8; ++i)
#pragma unroll
                for (int j = 0; j < 8; ++j) acc[i][j] = fmaf(a[i], b[j], acc[i][j]);
        }
        __syncthreads();
    }

    float bv0[8];
    *(float4*)&bv0[0] = *(const float4*)&bias[bn + tx * 8];
    *(float4*)&bv0[4] = *(const float4*)&bias[bn + tx * 8 + 4];
#pragma unroll
    for (int i = 0; i < 8; ++i) {
        float* dst = out + (size_t)(bm + ty * 8 + i) * DIM + bn + tx * 8;
        *(float4*)dst = make_float4(acc[i][0] + bv0[0], acc[i][1] + bv0[1],
                                    acc[i][2] + bv0[2], acc[i][3] + bv0[3]);
        *(float4*)(dst + 4) = make_float4(acc[i][4] + bv0[4], acc[i][5] + bv0[5],
                                          acc[i][6] + bv0[6], acc[i][7] + bv0[7]);
    }
}

extern "C" void kernel_launch(void* const* d_in, const int* in_sizes, int n_in,
                              void* d_out, int out_size) {
    const float* x     = (const float*)d_in[0];
    const float* w_qkv = (const float*)d_in[1];
    const float* w_out = (const float*)d_in[2];
    const float* b_out = (const float*)d_in[3];
    float* out = (float*)d_out;

    cudaFuncSetAttribute(flash_attn, cudaFuncAttributeMaxDynamicSharedMemorySize,
                         SMEM_ATTN);

    qkv_gemm<<<dim3(MTOT / 128, QKVN / 128), 256>>>(x, w_qkv);
    flash_attn<<<dim3(SEQ / 64, BATCH * HEADS), 256, SMEM_ATTN>>>();
    out_gemm<<<dim3(MTOT / 128, DIM / 128), 256>>>(w_out, b_out, out);
}

// round 3
// speedup vs baseline: 1.3524x; 1.3524x over previous
#include <cuda_runtime.h>
#include <cuda_bf16.h>
#include <stdint.h>
#include <math.h>

#define BATCH 4
#define SEQ   2048
#define DIM   1024
#define HEADS 16
#define DH    64
#define MTOT  (BATCH*SEQ)      // 8192
#define QKVN  (3*DIM)          // 3072

// Scratch (device globals: allocation-free per harness rules)
__device__ float g_Q[BATCH*HEADS*SEQ*DH];  // [b,h,n,d]
__device__ float g_K[BATCH*HEADS*SEQ*DH];
__device__ float g_V[BATCH*HEADS*SEQ*DH];
__device__ float g_O[BATCH*SEQ*DIM];       // [b,n,h*d]

// ===========================================================================
// helpers
// ===========================================================================
__device__ __forceinline__ uint32_t smem_u32(const void* p) {
    uint32_t a;
    asm("{ .reg .u64 t; cvta.to.shared.u64 t, %1; cvt.u32.u64 %0, t; }"
        : "=r"(a) : "l"(p));
    return a;
}

__device__ __forceinline__ void ldsm4(uint32_t* r, uint32_t addr) {
    asm volatile("ldmatrix.sync.aligned.m8n8.x4.shared.b16 {%0,%1,%2,%3}, [%4];"
                 : "=r"(r[0]), "=r"(r[1]), "=r"(r[2]), "=r"(r[3]) : "r"(addr));
}

__device__ __forceinline__ void mma16816(float* d, const uint32_t* a,
                                         const uint32_t* b) {
    asm volatile(
        "mma.sync.aligned.m16n8k16.row.col.f32.bf16.bf16.f32 "
        "{%0,%1,%2,%3}, {%4,%5,%6,%7}, {%8,%9}, {%0,%1,%2,%3};"
        : "+f"(d[0]), "+f"(d[1]), "+f"(d[2]), "+f"(d[3])
        : "r"(a[0]), "r"(a[1]), "r"(a[2]), "r"(a[3]), "r"(b[0]), "r"(b[1]));
}

__device__ __forceinline__ uint32_t pack_hi2(float a, float b) {
    __nv_bfloat162 t = __floats2bfloat162_rn(a, b);
    return *(uint32_t*)&t;
}
__device__ __forceinline__ uint32_t pack_lo2(float a, float b) {
    float ra = a - __bfloat162float(__float2bfloat16_rn(a));
    float rb = b - __bfloat162float(__float2bfloat16_rn(b));
    __nv_bfloat162 t = __floats2bfloat162_rn(ra, rb);
    return *(uint32_t*)&t;
}

// ===========================================================================
// bf16x3 GEMM on mma.sync. Block 128x128, BK=32, 8 warps (4m x 2n),
// warp tile 32x64. Double-buffered SMEM, 1 sync per chunk.
// MODE 0: A=x, W=w_qkv (LDW 3072), scatter epilogue into g_Q/g_K/g_V
// MODE 1: A=g_O, W=w_out (LDW 1024), C = A@W + bias -> out
// SMEM layout per stage (bytes): Ah[128][40h]=10240, Al=10240,
//                                Bh[128][40h]=10240 (as [n][k]), Bl=10240
// ===========================================================================
#define BK 32
#define NC (DIM / BK)          // 32
#define ROWH 40                // halves per row (32 data + 8 pad)
#define TILE_B (128 * ROWH * 2)  // 10240
#define STAGE (4 * TILE_B)       // 40960
#define SMEMG (2 * STAGE)        // 81920

template<int MODE>
__global__ __launch_bounds__(256) void mma_gemm(const float* __restrict__ Ain,
                                                const float* __restrict__ W,
                                                const float* __restrict__ bias,
                                                float* __restrict__ Cout) {
    extern __shared__ char smem[];
    const uint32_t smem_base = smem_u32(smem);
    const int LDW = (MODE == 0) ? QKVN : DIM;
    const float* A = (MODE == 0) ? Ain : g_O;

    const int tid = threadIdx.x;
    const int lane = tid & 31, w = tid >> 5;
    const int wm = w & 3, wn = w >> 2;
    const int bm = blockIdx.x * 128;
    const int bn = blockIdx.y * 128;

    // loader indices
    const int a_r = tid >> 1, a_q = (tid & 1) * 16;   // A: row, col-base
    const int b_n = tid & 127, b_k = (tid >> 7) * 16; // B: col(n), k-base

    float ar[16], br[16];

    // fragment smem offsets (bytes) precomputed
    const int a_row0 = wm * 32 + (lane & 15);
    const int a_colb = (lane >> 4) * 8;
    const int b_grp = lane >> 3, b_l8 = lane & 7;
    const int b_row0 = wn * 64 + ((b_grp >> 1) << 3) + b_l8;
    const int b_colb = (b_grp & 1) * 8;

    float acc[2][8][4];
#pragma unroll
    for (int i = 0; i < 2; ++i)
#pragma unroll
        for (int j = 0; j < 8; ++j)
#pragma unroll
            for (int k = 0; k < 4; ++k) acc[i][j][k] = 0.f;

#define GLOAD(c) do {                                                         \
    const float* ap = A + (size_t)(bm + a_r) * DIM + (c) * BK + a_q;          \
    _Pragma("unroll")                                                         \
    for (int j = 0; j < 4; ++j) *(float4*)&ar[j * 4] = *(const float4*)(ap + j * 4); \
    const float* bp = W + (size_t)((c) * BK + b_k) * LDW + bn + b_n;          \
    _Pragma("unroll")                                                         \
    for (int kk = 0; kk < 16; ++kk) br[kk] = bp[(size_t)kk * LDW];            \
} while (0)

#define SSTORE(s) do {                                                        \
    char* sb = smem + (s) * STAGE;                                            \
    _Pragma("unroll")                                                         \
    for (int j = 0; j < 4; ++j) {                                             \
        uint32_t hi0 = pack_hi2(ar[j*4], ar[j*4+1]);                          \
        uint32_t hi1 = pack_hi2(ar[j*4+2], ar[j*4+3]);                        \
        uint32_t lo0 = pack_lo2(ar[j*4], ar[j*4+1]);                          \
        uint32_t lo1 = pack_lo2(ar[j*4+2], ar[j*4+3]);                        \
        const int ho = a_r * ROWH + a_q + j * 4;                              \
        *(uint2*)(sb + ho * 2)          = make_uint2(hi0, hi1);               \
        *(uint2*)(sb + TILE_B + ho * 2) = make_uint2(lo0, lo1);               \
    }                                                                         \
    _Pragma("unroll")                                                         \
    for (int kk = 0; kk < 16; kk += 2) {                                      \
        uint32_t hi = pack_hi2(br[kk], br[kk+1]);                             \
        uint32_t lo = pack_lo2(br[kk], br[kk+1]);                             \
        const int ho = b_n * ROWH + b_k + kk;                                 \
        *(uint32_t*)(sb + 2 * TILE_B + ho * 2) = hi;                          \
        *(uint32_t*)(sb + 3 * TILE_B + ho * 2) = lo;                          \
    }                                                                         \
} while (0)

    GLOAD(0);
    SSTORE(0);
    __syncthreads();

    for (int c = 0; c < NC; ++c) {
        if (c + 1 < NC) GLOAD(c + 1);

        const uint32_t base = smem_base + (c & 1) * STAGE;
#pragma unroll
        for (int ks = 0; ks < 2; ++ks) {
            uint32_t ah[2][4], al[2][4], bh[4][4], bl[4][4];
#pragma unroll
            for (int tm = 0; tm < 2; ++tm) {
                const uint32_t off =
                    ((a_row0 + tm * 16) * ROWH + ks * 16 + a_colb) * 2;
                ldsm4(ah[tm], base + off);
                ldsm4(al[tm], base + TILE_B + off);
            }
#pragma unroll
            for (int t2 = 0; t2 < 4; ++t2) {
                const uint32_t off =
                    ((b_row0 + t2 * 16) * ROWH + ks * 16 + b_colb) * 2;
                ldsm4(bh[t2], base + 2 * TILE_B + off);
                ldsm4(bl[t2], base + 3 * TILE_B + off);
            }
#pragma unroll
            for (int tm = 0; tm < 2; ++tm)
#pragma unroll
                for (int tn = 0; tn < 8; ++tn) {
                    const uint32_t* bhp = &bh[tn >> 1][(tn & 1) * 2];
                    const uint32_t* blp = &bl[tn >> 1][(tn & 1) * 2];
                    mma16816(acc[tm][tn], ah[tm], bhp);
                    mma16816(acc[tm][tn], ah[tm], blp);
                    mma16816(acc[tm][tn], al[tm], bhp);
                }
        }

        if (c + 1 < NC) SSTORE((c + 1) & 1);
        __syncthreads();
    }

    // Epilogue
    const int r0 = bm + wm * 32 + (lane >> 2);
    const int c0b = wn * 64 + (lane & 3) * 2;
    if (MODE == 0) {
        const int sec = bn >> 10;
        float* Gp = (sec == 0) ? g_Q : (sec == 1 ? g_K : g_V);
        const int innerb = (bn & 1023) + c0b;
#pragma unroll
        for (int tm = 0; tm < 2; ++tm)
#pragma unroll
            for (int tn = 0; tn < 8; ++tn) {
                const int inner = innerb + tn * 8;
                const int h = inner >> 6, d = inner & 63;
#pragma unroll
                for (int rr = 0; rr < 2; ++rr) {
                    const int m = r0 + tm * 16 + rr * 8;
                    const int bb = m >> 11, nn = m & (SEQ - 1);
                    float* dst =
                        Gp + (((size_t)(bb * HEADS + h) * SEQ + nn) * DH + d);
                    *(float2*)dst =
                        make_float2(acc[tm][tn][rr * 2], acc[tm][tn][rr * 2 + 1]);
                }
            }
    } else {
#pragma unroll
        for (int tm = 0; tm < 2; ++tm)
#pragma unroll
            for (int tn = 0; tn < 8; ++tn) {
                const int cc = bn + c0b + tn * 8;
                float2 bv = *(const float2*)(bias + cc);
#pragma unroll
                for (int rr = 0; rr < 2; ++rr) {
                    const int m = r0 + tm * 16 + rr * 8;
                    float* dst = Cout + (size_t)m * DIM + cc;
                    *(float2*)dst = make_float2(acc[tm][tn][rr * 2] + bv.x,
                                                acc[tm][tn][rr * 2 + 1] + bv.y);
                }
            }
    }
#undef GLOAD
#undef SSTORE
}

// ===========================================================================
// Kernel 2: flash attention, fp32 (unchanged from R1)
// ===========================================================================
#define SROW 68
#define SMEM_ATTN (3 * 64 * SROW * 4)

__global__ __launch_bounds__(256) void flash_attn() {
    extern __shared__ float sm[];
    float* Qs = sm;
    float* Kt = sm + 64 * SROW;
    float* Vs = sm + 2 * 64 * SROW;

    const int tid = threadIdx.x;
    const int tx = tid & 15, ty = tid >> 4;
    const int ty4 = ty * 4, tx4 = tx * 4;
    const int bh = blockIdx.y;
    const int q0 = blockIdx.x * 64;
    const float* Qg = g_Q + (size_t)bh * SEQ * DH;
    const float* Kg = g_K + (size_t)bh * SEQ * DH;
    const float* Vg = g_V + (size_t)bh * SEQ * DH;
    const float scale = 0.125f;

#pragma unroll
    for (int it = 0; it < 4; ++it) {
        int i = tid + it * 256;
        int r = i >> 4, c4 = (i & 15) << 2;
        float4 v = *(const float4*)&Qg[(size_t)(q0 + r) * DH + c4];
        *(float4*)&Qs[r * SROW + c4] =
            make_float4(v.x * scale, v.y * scale, v.z * scale, v.w * scale);
    }
    __syncthreads();

    float m[4], l[4], o[4][4];
#pragma unroll
    for (int i = 0; i < 4; ++i) {
        m[i] = -1e30f; l[i] = 0.f;
#pragma unroll
        for (int j = 0; j < 4; ++j) o[i][j] = 0.f;
    }

    for (int kv0 = 0; kv0 < SEQ; kv0 += 64) {
        __syncthreads();
#pragma unroll
        for (int it = 0; it < 4; ++it) {
            int i = tid + it * 256;
            int r = i >> 4, c4 = (i & 15) << 2;
            float4 kv = *(const float4*)&Kg[(size_t)(kv0 + r) * DH + c4];
            Kt[(c4 + 0) * SROW + r] = kv.x;
            Kt[(c4 + 1) * SROW + r] = kv.y;
            Kt[(c4 + 2) * SROW + r] = kv.z;
            Kt[(c4 + 3) * SROW + r] = kv.w;
            float4 vv = *(const float4*)&Vg[(size_t)(kv0 + r) * DH + c4];
            *(float4*)&Vs[r * SROW + c4] = vv;
        }
        __syncthreads();

        float s[4][4];
#pragma unroll
        for (int i = 0; i < 4; ++i)
#pragma unroll
            for (int j = 0; j < 4; ++j) s[i][j] = 0.f;
#pragma unroll
        for (int kk = 0; kk < 64; kk += 4) {
            float qa[4][4], kb[4][4];
#pragma unroll
            for (int i = 0; i < 4; ++i)
                *(float4*)&qa[i][0] = *(const float4*)&Qs[(ty4 + i) * SROW + kk];
#pragma unroll
            for (int t = 0; t < 4; ++t)
                *(float4*)&kb[t][0] = *(const float4*)&Kt[(kk + t) * SROW + tx4];
#pragma unroll
            for (int i = 0; i < 4; ++i)
#pragma unroll
                for (int j = 0; j < 4; ++j) {
                    s[i][j] = fmaf(qa[i][0], kb[0][j], s[i][j]);
                    s[i][j] = fmaf(qa[i][1], kb[1][j], s[i][j]);
                    s[i][j] = fmaf(qa[i][2], kb[2][j], s[i][j]);
                    s[i][j] = fmaf(qa[i][3], kb[3][j], s[i][j]);
                }
        }
        __syncthreads();

#pragma unroll
        for (int i = 0; i < 4; ++i) {
            float mx = fmaxf(fmaxf(s[i][0], s[i][1]), fmaxf(s[i][2], s[i][3]));
#pragma unroll
            for (int off = 1; off < 16; off <<= 1)
                mx = fmaxf(mx, __shfl_xor_sync(0xffffffffu, mx, off));
            float mn = fmaxf(m[i], mx);
            float sum = 0.f;
#pragma unroll
            for (int j = 0; j < 4; ++j) {
                float p = __expf(s[i][j] - mn);
                s[i][j] = p;
                sum += p;
            }
#pragma unroll
            for (int off = 1; off < 16; off <<= 1)
                sum += __shfl_xor_sync(0xffffffffu, sum, off);
            float alpha = __expf(m[i] - mn);
            l[i] = l[i] * alpha + sum;
            m[i] = mn;
#pragma unroll
            for (int j = 0; j < 4; ++j) o[i][j] *= alpha;
        }

#pragma unroll
        for (int i = 0; i < 4; ++i)
            *(float4*)&Kt[(ty4 + i) * SROW + tx4] =
                make_float4(s[i][0], s[i][1], s[i][2], s[i][3]);
        __syncthreads();

#pragma unroll
        for (int kk = 0; kk < 64; kk += 4) {
            float pa[4][4], vb[4][4];
#pragma unroll
            for (int i = 0; i < 4; ++i)
                *(float4*)&pa[i][0] = *(const float4*)&Kt[(ty4 + i) * SROW + kk];
#pragma unroll
            for (int t = 0; t < 4; ++t)
                *(float4*)&vb[t][0] = *(const float4*)&Vs[(kk + t) * SROW + tx4];
#pragma unroll
            for (int i = 0; i < 4; ++i)
#pragma unroll
                for (int j = 0; j < 4; ++j) {
                    o[i][j] = fmaf(pa[i][0], vb[0][j], o[i][j]);
                    o[i][j] = fmaf(pa[i][1], vb[1][j], o[i][j]);
                    o[i][j] = fmaf(pa[i][2], vb[2][j], o[i][j]);
                    o[i][j] = fmaf(pa[i][3], vb[3][j], o[i][j]);
                }
        }
    }

    const int bb = bh >> 4, hh = bh & 15;
#pragma unroll
    for (int i = 0; i < 4; ++i) {
        float inv = 1.f / l[i];
        int n = q0 + ty4 + i;
        float* dst = g_O + ((size_t)(bb * SEQ + n) * DIM + hh * DH + tx4);
        *(float4*)dst = make_float4(o[i][0] * inv, o[i][1] * inv,
                                    o[i][2] * inv, o[i][3] * inv);
    }
}

extern "C" void kernel_launch(void* const* d_in, const int* in_sizes, int n_in,
                              void* d_out, int out_size) {
    const float* x     = (const float*)d_in[0];
    const float* w_qkv = (const float*)d_in[1];
    const float* w_out = (const float*)d_in[2];
    const float* b_out = (const float*)d_in[3];
    float* out = (float*)d_out;

    cudaFuncSetAttribute(mma_gemm<0>, cudaFuncAttributeMaxDynamicSharedMemorySize,
                         SMEMG);
    cudaFuncSetAttribute(mma_gemm<1>, cudaFuncAttributeMaxDynamicSharedMemorySize,
                         SMEMG);
    cudaFuncSetAttribute(flash_attn, cudaFuncAttributeMaxDynamicSharedMemorySize,
                         SMEM_ATTN);

    mma_gemm<0><<<dim3(MTOT / 128, QKVN / 128), 256, SMEMG>>>(x, w_qkv, nullptr, nullptr);
    flash_attn<<<dim3(SEQ / 64, BATCH * HEADS), 256, SMEM_ATTN>>>();
    mma_gemm<1><<<dim3(MTOT / 128, DIM / 128), 256, SMEMG>>>(nullptr, w_out, b_out, out);
}

// round 4
// speedup vs baseline: 2.8084x; 2.0766x over previous
#include <cuda_runtime.h>
#include <cuda_bf16.h>
#include <stdint.h>
#include <math.h>

#define BATCH 4
#define SEQ   2048
#define DIM   1024
#define HEADS 16
#define DH    64
#define MTOT  (BATCH*SEQ)      // 8192
#define QKVN  (3*DIM)          // 3072

// Scratch (device globals)
__device__ __nv_bfloat16 g_Qh[BATCH*HEADS*SEQ*DH], g_Ql[BATCH*HEADS*SEQ*DH];
__device__ __nv_bfloat16 g_Kh[BATCH*HEADS*SEQ*DH], g_Kl[BATCH*HEADS*SEQ*DH];
__device__ __nv_bfloat16 g_Vth[BATCH*HEADS*SEQ*DH], g_Vtl[BATCH*HEADS*SEQ*DH]; // [b,h,d,n]
__device__ float g_O[BATCH*SEQ*DIM];       // [b,n,h*d]

// ===========================================================================
// helpers
// ===========================================================================
__device__ __forceinline__ uint32_t smem_u32(const void* p) {
    uint32_t a;
    asm("{ .reg .u64 t; cvta.to.shared.u64 t, %1; cvt.u32.u64 %0, t; }"
        : "=r"(a) : "l"(p));
    return a;
}

__device__ __forceinline__ void ldsm4(uint32_t* r, uint32_t addr) {
    asm volatile("ldmatrix.sync.aligned.m8n8.x4.shared.b16 {%0,%1,%2,%3}, [%4];"
                 : "=r"(r[0]), "=r"(r[1]), "=r"(r[2]), "=r"(r[3]) : "r"(addr));
}

__device__ __forceinline__ void mma16816(float* d, const uint32_t* a,
                                         const uint32_t* b) {
    asm volatile(
        "mma.sync.aligned.m16n8k16.row.col.f32.bf16.bf16.f32 "
        "{%0,%1,%2,%3}, {%4,%5,%6,%7}, {%8,%9}, {%0,%1,%2,%3};"
        : "+f"(d[0]), "+f"(d[1]), "+f"(d[2]), "+f"(d[3])
        : "r"(a[0]), "r"(a[1]), "r"(a[2]), "r"(a[3]), "r"(b[0]), "r"(b[1]));
}

__device__ __forceinline__ uint32_t pack_hi2(float a, float b) {
    __nv_bfloat162 t = __floats2bfloat162_rn(a, b);
    return *(uint32_t*)&t;
}
__device__ __forceinline__ uint32_t pack_lo2(float a, float b) {
    float ra = a - __bfloat162float(__float2bfloat16_rn(a));
    float rb = b - __bfloat162float(__float2bfloat16_rn(b));
    __nv_bfloat162 t = __floats2bfloat162_rn(ra, rb);
    return *(uint32_t*)&t;
}
__device__ __forceinline__ __nv_bfloat16 bf_hi(float v) {
    return __float2bfloat16_rn(v);
}
__device__ __forceinline__ __nv_bfloat16 bf_lo(float v) {
    return __float2bfloat16_rn(v - __bfloat162float(__float2bfloat16_rn(v)));
}

#define CP16(s, g) asm volatile("cp.async.cg.shared.global [%0], [%1], 16;" \
                                :: "r"(s), "l"(g) : "memory")
#define CPCOMMIT() asm volatile("cp.async.commit_group;" ::: "memory")
#define CPWAIT0()  asm volatile("cp.async.wait_group 0;" ::: "memory")

// ===========================================================================
// bf16x3 GEMM on mma.sync (as R3). MODE 0 epilogue now writes bf16 hi/lo
// Q/K (row-major per head, Q pre-scaled) and V transposed [b,h,d,n].
// ===========================================================================
#define BK 32
#define NC (DIM / BK)          // 32
#define ROWH 40
#define TILE_B (128 * ROWH * 2)
#define STAGE (4 * TILE_B)
#define SMEMG (2 * STAGE)

template<int MODE>
__global__ __launch_bounds__(256) void mma_gemm(const float* __restrict__ Ain,
                                                const float* __restrict__ W,
                                                const float* __restrict__ bias,
                                                float* __restrict__ Cout) {
    extern __shared__ char smem[];
    const uint32_t smem_base = smem_u32(smem);
    const int LDW = (MODE == 0) ? QKVN : DIM;
    const float* A = (MODE == 0) ? Ain : g_O;

    const int tid = threadIdx.x;
    const int lane = tid & 31, w = tid >> 5;
    const int wm = w & 3, wn = w >> 2;
    const int bm = blockIdx.x * 128;
    const int bn = blockIdx.y * 128;

    const int a_r = tid >> 1, a_q = (tid & 1) * 16;
    const int b_n = tid & 127, b_k = (tid >> 7) * 16;

    float ar[16], br[16];

    const int a_row0 = wm * 32 + (lane & 15);
    const int a_colb = (lane >> 4) * 8;
    const int b_grp = lane >> 3, b_l8 = lane & 7;
    const int b_row0 = wn * 64 + ((b_grp >> 1) << 3) + b_l8;
    const int b_colb = (b_grp & 1) * 8;

    float acc[2][8][4];
#pragma unroll
    for (int i = 0; i < 2; ++i)
#pragma unroll
        for (int j = 0; j < 8; ++j)
#pragma unroll
            for (int k = 0; k < 4; ++k) acc[i][j][k] = 0.f;

#define GLOAD(c) do {                                                         \
    const float* ap = A + (size_t)(bm + a_r) * DIM + (c) * BK + a_q;          \
    _Pragma("unroll")                                                         \
    for (int j = 0; j < 4; ++j) *(float4*)&ar[j * 4] = *(const float4*)(ap + j * 4); \
    const float* bp = W + (size_t)((c) * BK + b_k) * LDW + bn + b_n;          \
    _Pragma("unroll")                                                         \
    for (int kk = 0; kk < 16; ++kk) br[kk] = bp[(size_t)kk * LDW];            \
} while (0)

#define SSTORE(s) do {                                                        \
    char* sb = smem + (s) * STAGE;                                            \
    _Pragma("unroll")                                                         \
    for (int j = 0; j < 4; ++j) {                                             \
        uint32_t hi0 = pack_hi2(ar[j*4], ar[j*4+1]);                          \
        uint32_t hi1 = pack_hi2(ar[j*4+2], ar[j*4+3]);                        \
        uint32_t lo0 = pack_lo2(ar[j*4], ar[j*4+1]);                          \
        uint32_t lo1 = pack_lo2(ar[j*4+2], ar[j*4+3]);                        \
        const int ho = a_r * ROWH + a_q + j * 4;                              \
        *(uint2*)(sb + ho * 2)          = make_uint2(hi0, hi1);               \
        *(uint2*)(sb + TILE_B + ho * 2) = make_uint2(lo0, lo1);               \
    }                                                                         \
    _Pragma("unroll")                                                         \
    for (int kk = 0; kk < 16; kk += 2) {                                      \
        uint32_t hi = pack_hi2(br[kk], br[kk+1]);                             \
        uint32_t lo = pack_lo2(br[kk], br[kk+1]);                             \
        const int ho = b_n * ROWH + b_k + kk;                                 \
        *(uint32_t*)(sb + 2 * TILE_B + ho * 2) = hi;                          \
        *(uint32_t*)(sb + 3 * TILE_B + ho * 2) = lo;                          \
    }                                                                         \
} while (0)

    GLOAD(0);
    SSTORE(0);
    __syncthreads();

    for (int c = 0; c < NC; ++c) {
        if (c + 1 < NC) GLOAD(c + 1);

        const uint32_t base = smem_base + (c & 1) * STAGE;
#pragma unroll
        for (int ks = 0; ks < 2; ++ks) {
            uint32_t ah[2][4], al[2][4], bh[4][4], bl[4][4];
#pragma unroll
            for (int tm = 0; tm < 2; ++tm) {
                const uint32_t off =
                    ((a_row0 + tm * 16) * ROWH + ks * 16 + a_colb) * 2;
                ldsm4(ah[tm], base + off);
                ldsm4(al[tm], base + TILE_B + off);
            }
#pragma unroll
            for (int t2 = 0; t2 < 4; ++t2) {
                const uint32_t off =
                    ((b_row0 + t2 * 16) * ROWH + ks * 16 + b_colb) * 2;
                ldsm4(bh[t2], base + 2 * TILE_B + off);
                ldsm4(bl[t2], base + 3 * TILE_B + off);
            }
#pragma unroll
            for (int tm = 0; tm < 2; ++tm)
#pragma unroll
                for (int tn = 0; tn < 8; ++tn) {
                    const uint32_t* bhp = &bh[tn >> 1][(tn & 1) * 2];
                    const uint32_t* blp = &bl[tn >> 1][(tn & 1) * 2];
                    mma16816(acc[tm][tn], ah[tm], bhp);
                    mma16816(acc[tm][tn], ah[tm], blp);
                    mma16816(acc[tm][tn], al[tm], bhp);
                }
        }

        if (c + 1 < NC) SSTORE((c + 1) & 1);
        __syncthreads();
    }

    const int r0 = bm + wm * 32 + (lane >> 2);
    const int c0b = wn * 64 + (lane & 3) * 2;
    if (MODE == 0) {
        const int sec = bn >> 10;
        const int innerb = (bn & 1023) + c0b;
#pragma unroll
        for (int tm = 0; tm < 2; ++tm)
#pragma unroll
            for (int tn = 0; tn < 8; ++tn) {
                const int inner = innerb + tn * 8;
                const int h = inner >> 6, d = inner & 63;
#pragma unroll
                for (int rr = 0; rr < 2; ++rr) {
                    const int mrow = r0 + tm * 16 + rr * 8;
                    const int bb = mrow >> 11, nn = mrow & (SEQ - 1);
                    float v0 = acc[tm][tn][rr * 2], v1 = acc[tm][tn][rr * 2 + 1];
                    const size_t bhh = (size_t)(bb * HEADS + h);
                    if (sec == 0) {
                        v0 *= 0.125f; v1 *= 0.125f;
                        const size_t ib = (bhh * SEQ + nn) * DH + d;
                        *(uint32_t*)&g_Qh[ib] = pack_hi2(v0, v1);
                        *(uint32_t*)&g_Ql[ib] = pack_lo2(v0, v1);
                    } else if (sec == 1) {
                        const size_t ib = (bhh * SEQ + nn) * DH + d;
                        *(uint32_t*)&g_Kh[ib] = pack_hi2(v0, v1);
                        *(uint32_t*)&g_Kl[ib] = pack_lo2(v0, v1);
                    } else {
                        const size_t tb = (bhh * DH + d) * SEQ + nn;
                        g_Vth[tb] = bf_hi(v0);       g_Vtl[tb] = bf_lo(v0);
                        g_Vth[tb + SEQ] = bf_hi(v1); g_Vtl[tb + SEQ] = bf_lo(v1);
                    }
                }
            }
    } else {
#pragma unroll
        for (int tm = 0; tm < 2; ++tm)
#pragma unroll
            for (int tn = 0; tn < 8; ++tn) {
                const int cc = bn + c0b + tn * 8;
                float2 bv = *(const float2*)(bias + cc);
#pragma unroll
                for (int rr = 0; rr < 2; ++rr) {
                    const int mrow = r0 + tm * 16 + rr * 8;
                    float* dst = Cout + (size_t)mrow * DIM + cc;
                    *(float2*)dst = make_float2(acc[tm][tn][rr * 2] + bv.x,
                                                acc[tm][tn][rr * 2 + 1] + bv.y);
                }
            }
    }
#undef GLOAD
#undef SSTORE
}

// ===========================================================================
// Flash attention on mma.sync, bf16x3. 128 q-rows/block, 8 warps (16 rows
// each), kv tiles of 64, cp.async double-buffered K/V.
// SMEM: Qh[128][72] Ql[128][72] | 2 stages of {Kh,Kl,Vth,Vtl}[64][72]
// ===========================================================================
#define ASTR 72
#define AQH 0
#define AQL 18432
#define ASTG 36864
#define ASTGSZ 36864
#define SMEM_FA (ASTG + 2 * ASTGSZ)   // 110592

__global__ __launch_bounds__(256) void flash_mma() {
    extern __shared__ char smf[];
    const uint32_t sb = smem_u32(smf);
    const int tid = threadIdx.x;
    const int lane = tid & 31, w = tid >> 5;
    const int bh = blockIdx.y;
    const int q0 = blockIdx.x * 128;

    // async Q load
    {
        const size_t qb = ((size_t)bh * SEQ + q0) * DH;
#pragma unroll
        for (int it = 0; it < 4; ++it) {
            const int i = tid + it * 256;
            const int r = i >> 3, cc = i & 7;
            const uint32_t so = sb + (uint32_t)(r * ASTR + cc * 8) * 2;
            const size_t gi = qb + (size_t)r * DH + cc * 8;
            CP16(so + AQH, (const char*)(g_Qh + gi));
            CP16(so + AQL, (const char*)(g_Ql + gi));
        }
    }

#define LOADSTG(st, kv0) do {                                                 \
    _Pragma("unroll")                                                         \
    for (int it = 0; it < 2; ++it) {                                          \
        const int i = tid + it * 256;                                         \
        const int r = i >> 3, cc = i & 7;                                     \
        const uint32_t so = sb + ASTG + (st) * ASTGSZ +                       \
                            (uint32_t)(r * ASTR + cc * 8) * 2;                \
        const size_t ki = ((size_t)bh * SEQ + (kv0) + r) * DH + cc * 8;       \
        CP16(so,         (const char*)(g_Kh + ki));                           \
        CP16(so + 9216,  (const char*)(g_Kl + ki));                           \
        const size_t vi = ((size_t)bh * DH + r) * SEQ + (kv0) + cc * 8;       \
        CP16(so + 18432, (const char*)(g_Vth + vi));                          \
        CP16(so + 27648, (const char*)(g_Vtl + vi));                          \
    }                                                                         \
    CPCOMMIT();                                                               \
} while (0)

    LOADSTG(0, 0);

    const int a_row = w * 16 + (lane & 15);
    const uint32_t a_off = (uint32_t)(a_row * ASTR + (lane >> 4) * 8) * 2;
    const int b_grp = lane >> 3, b_l8 = lane & 7;
    const int b_row0 = ((b_grp >> 1) << 3) + b_l8;
    const int b_colb = (b_grp & 1) * 8;

    float m0 = -1e30f, m1 = -1e30f, l0 = 0.f, l1 = 0.f;
    float O[8][4];
#pragma unroll
    for (int j = 0; j < 8; ++j)
#pragma unroll
        for (int k = 0; k < 4; ++k) O[j][k] = 0.f;

    for (int c = 0; c < 32; ++c) {
        CPWAIT0();
        __syncthreads();
        if (c + 1 < 32) LOADSTG((c + 1) & 1, (c + 1) * 64);

        const uint32_t kb = sb + ASTG + (c & 1) * ASTGSZ;

        // ---- S = Q K^T (bf16x3) ----
        float S[8][4];
#pragma unroll
        for (int j = 0; j < 8; ++j)
#pragma unroll
            for (int k = 0; k < 4; ++k) S[j][k] = 0.f;
#pragma unroll
        for (int ks = 0; ks < 4; ++ks) {
            uint32_t ah[4], al[4];
            ldsm4(ah, sb + AQH + a_off + ks * 32);
            ldsm4(al, sb + AQL + a_off + ks * 32);
            uint32_t kh4[4][4], kl4[4][4];
#pragma unroll
            for (int t2 = 0; t2 < 4; ++t2) {
                const uint32_t off =
                    (uint32_t)((b_row0 + t2 * 16) * ASTR + ks * 16 + b_colb) * 2;
                ldsm4(kh4[t2], kb + off);
                ldsm4(kl4[t2], kb + 9216 + off);
            }
#pragma unroll
            for (int tn = 0; tn < 8; ++tn) {
                const uint32_t* bhp = &kh4[tn >> 1][(tn & 1) * 2];
                const uint32_t* blp = &kl4[tn >> 1][(tn & 1) * 2];
                mma16816(S[tn], ah, bhp);
                mma16816(S[tn], ah, blp);
                mma16816(S[tn], al, bhp);
            }
        }

        // ---- online softmax ----
        float mx0 = -1e30f, mx1 = -1e30f;
#pragma unroll
        for (int tn = 0; tn < 8; ++tn) {
            mx0 = fmaxf(mx0, fmaxf(S[tn][0], S[tn][1]));
            mx1 = fmaxf(mx1, fmaxf(S[tn][2], S[tn][3]));
        }
        mx0 = fmaxf(mx0, __shfl_xor_sync(0xffffffffu, mx0, 1));
        mx0 = fmaxf(mx0, __shfl_xor_sync(0xffffffffu, mx0, 2));
        mx1 = fmaxf(mx1, __shfl_xor_sync(0xffffffffu, mx1, 1));
        mx1 = fmaxf(mx1, __shfl_xor_sync(0xffffffffu, mx1, 2));
        const float mn0 = fmaxf(m0, mx0), mn1 = fmaxf(m1, mx1);
        float s0 = 0.f, s1 = 0.f;
#pragma unroll
        for (int tn = 0; tn < 8; ++tn) {
            S[tn][0] = __expf(S[tn][0] - mn0); s0 += S[tn][0];
            S[tn][1] = __expf(S[tn][1] - mn0); s0 += S[tn][1];
            S[tn][2] = __expf(S[tn][2] - mn1); s1 += S[tn][2];
            S[tn][3] = __expf(S[tn][3] - mn1); s1 += S[tn][3];
        }
        s0 += __shfl_xor_sync(0xffffffffu, s0, 1);
        s0 += __shfl_xor_sync(0xffffffffu, s0, 2);
        s1 += __shfl_xor_sync(0xffffffffu, s1, 1);
        s1 += __shfl_xor_sync(0xffffffffu, s1, 2);
        const float al0 = __expf(m0 - mn0), al1 = __expf(m1 - mn1);
        m0 = mn0; m1 = mn1;
        l0 = l0 * al0 + s0;
        l1 = l1 * al1 + s1;
#pragma unroll
        for (int tn = 0; tn < 8; ++tn) {
            O[tn][0] *= al0; O[tn][1] *= al0;
            O[tn][2] *= al1; O[tn][3] *= al1;
        }

        // ---- pack P (hi/lo) as A-fragments ----
        uint32_t pa[4][4], pl[4][4];
#pragma unroll
        for (int ks = 0; ks < 4; ++ks) {
            pa[ks][0] = pack_hi2(S[2*ks][0],   S[2*ks][1]);
            pa[ks][1] = pack_hi2(S[2*ks][2],   S[2*ks][3]);
            pa[ks][2] = pack_hi2(S[2*ks+1][0], S[2*ks+1][1]);
            pa[ks][3] = pack_hi2(S[2*ks+1][2], S[2*ks+1][3]);
            pl[ks][0] = pack_lo2(S[2*ks][0],   S[2*ks][1]);
            pl[ks][1] = pack_lo2(S[2*ks][2],   S[2*ks][3]);
            pl[ks][2] = pack_lo2(S[2*ks+1][0], S[2*ks+1][1]);
            pl[ks][3] = pack_lo2(S[2*ks+1][2], S[2*ks+1][3]);
        }

        // ---- O += P V (bf16x3) ----
#pragma unroll
        for (int ks = 0; ks < 4; ++ks) {
            uint32_t vh4[4][4], vl4[4][4];
#pragma unroll
            for (int t2 = 0; t2 < 4; ++t2) {
                const uint32_t off =
                    (uint32_t)((b_row0 + t2 * 16) * ASTR + ks * 16 + b_colb) * 2;
                ldsm4(vh4[t2], kb + 18432 + off);
                ldsm4(vl4[t2], kb + 27648 + off);
            }
#pragma unroll
            for (int tn = 0; tn < 8; ++tn) {
                const uint32_t* bhp = &vh4[tn >> 1][(tn & 1) * 2];
                const uint32_t* blp = &vl4[tn >> 1][(tn & 1) * 2];
                mma16816(O[tn], pa[ks], bhp);
                mma16816(O[tn], pa[ks], blp);
                mma16816(O[tn], pl[ks], bhp);
            }
        }
    }

    // ---- epilogue: normalize, write g_O [b, n, h*64] ----
    const int bb = bh >> 4, hh = bh & 15;
    const float inv0 = 1.f / l0, inv1 = 1.f / l1;
    const int r0g = q0 + w * 16 + (lane >> 2);
    const int cb = hh * 64 + (lane & 3) * 2;
#pragma unroll
    for (int tn = 0; tn < 8; ++tn) {
        float* d0 = g_O + ((size_t)(bb * SEQ + r0g) * DIM + cb + tn * 8);
        *(float2*)d0 = make_float2(O[tn][0] * inv0, O[tn][1] * inv0);
        float* d1 = g_O + ((size_t)(bb * SEQ + r0g + 8) * DIM + cb + tn * 8);
        *(float2*)d1 = make_float2(O[tn][2] * inv1, O[tn][3] * inv1);
    }
#undef LOADSTG
}

extern "C" void kernel_launch(void* const* d_in, const int* in_sizes, int n_in,
                              void* d_out, int out_size) {
    const float* x     = (const float*)d_in[0];
    const float* w_qkv = (const float*)d_in[1];
    const float* w_out = (const float*)d_in[2];
    const float* b_out = (const float*)d_in[3];
    float* out = (float*)d_out;

    cudaFuncSetAttribute(mma_gemm<0>, cudaFuncAttributeMaxDynamicSharedMemorySize,
                         SMEMG);
    cudaFuncSetAttribute(mma_gemm<1>, cudaFuncAttributeMaxDynamicSharedMemorySize,
                         SMEMG);
    cudaFuncSetAttribute(flash_mma, cudaFuncAttributeMaxDynamicSharedMemorySize,
                         SMEM_FA);

    mma_gemm<0><<<dim3(MTOT / 128, QKVN / 128), 256, SMEMG>>>(x, w_qkv, nullptr, nullptr);
    flash_mma<<<dim3(SEQ / 128, BATCH * HEADS), 256, SMEM_FA>>>();
    mma_gemm<1><<<dim3(MTOT / 128, DIM / 128), 256, SMEMG>>>(nullptr, w_out, b_out, out);
}

// round 6
// speedup vs baseline: 3.1973x; 1.1385x over previous
#include <cuda_runtime.h>
#include <cuda_bf16.h>
#include <stdint.h>
#include <math.h>

#define BATCH 4
#define SEQ   2048
#define DIM   1024
#define HEADS 16
#define DH    64
#define MTOT  (BATCH*SEQ)      // 8192
#define QKVN  (3*DIM)          // 3072

// Scratch (device globals)
__device__ __nv_bfloat16 g_xh[MTOT*DIM],  g_xl[MTOT*DIM];          // x hi/lo
__device__ __nv_bfloat16 g_wqh[QKVN*DIM], g_wql[QKVN*DIM];         // w_qkv^T [n][k]
__device__ __nv_bfloat16 g_woh[DIM*DIM],  g_wol[DIM*DIM];          // w_out^T [n][k]
__device__ __nv_bfloat16 g_Qh[BATCH*HEADS*SEQ*DH], g_Ql[BATCH*HEADS*SEQ*DH];
__device__ __nv_bfloat16 g_Kh[BATCH*HEADS*SEQ*DH], g_Kl[BATCH*HEADS*SEQ*DH];
__device__ __nv_bfloat16 g_Vth[BATCH*HEADS*SEQ*DH], g_Vtl[BATCH*HEADS*SEQ*DH]; // [b,h,d,n]
__device__ __nv_bfloat16 g_Oh[BATCH*SEQ*DIM], g_Ol[BATCH*SEQ*DIM]; // [b,n,h*d]

// ===========================================================================
// helpers
// ===========================================================================
__device__ __forceinline__ uint32_t smem_u32(const void* p) {
    uint32_t a;
    asm("{ .reg .u64 t; cvta.to.shared.u64 t, %1; cvt.u32.u64 %0, t; }"
        : "=r"(a) : "l"(p));
    return a;
}

__device__ __forceinline__ void ldsm4(uint32_t* r, uint32_t addr) {
    asm volatile("ldmatrix.sync.aligned.m8n8.x4.shared.b16 {%0,%1,%2,%3}, [%4];"
                 : "=r"(r[0]), "=r"(r[1]), "=r"(r[2]), "=r"(r[3]) : "r"(addr));
}

__device__ __forceinline__ void mma16816(float* d, const uint32_t* a,
                                         const uint32_t* b) {
    asm volatile(
        "mma.sync.aligned.m16n8k16.row.col.f32.bf16.bf16.f32 "
        "{%0,%1,%2,%3}, {%4,%5,%6,%7}, {%8,%9}, {%0,%1,%2,%3};"
        : "+f"(d[0]), "+f"(d[1]), "+f"(d[2]), "+f"(d[3])
        : "r"(a[0]), "r"(a[1]), "r"(a[2]), "r"(a[3]), "r"(b[0]), "r"(b[1]));
}

__device__ __forceinline__ uint32_t pack_hi2(float a, float b) {
    __nv_bfloat162 t = __floats2bfloat162_rn(a, b);
    return *(uint32_t*)&t;
}
__device__ __forceinline__ uint32_t pack_lo2(float a, float b) {
    float ra = a - __bfloat162float(__float2bfloat16_rn(a));
    float rb = b - __bfloat162float(__float2bfloat16_rn(b));
    __nv_bfloat162 t = __floats2bfloat162_rn(ra, rb);
    return *(uint32_t*)&t;
}
__device__ __forceinline__ __nv_bfloat16 bf_hi(float v) {
    return __float2bfloat16_rn(v);
}
__device__ __forceinline__ __nv_bfloat16 bf_lo(float v) {
    return __float2bfloat16_rn(v - __bfloat162float(__float2bfloat16_rn(v)));
}

#define CP16(s, g) asm volatile("cp.async.cg.shared.global [%0], [%1], 16;" \
                                :: "r"(s), "l"(g) : "memory")
#define CPCOMMIT() asm volatile("cp.async.commit_group;" ::: "memory")
#define CPWAIT0()  asm volatile("cp.async.wait_group 0;" ::: "memory")
#define CPWAIT1()  asm volatile("cp.async.wait_group 1;" ::: "memory")

// ===========================================================================
// Prep kernels — destinations are referenced DIRECTLY as device globals
// (no device-symbol pointers passed from host; that was the R5 bug).
// ===========================================================================
__global__ __launch_bounds__(256) void conv_x(const float4* __restrict__ x) {
    const size_t i = (size_t)blockIdx.x * 256 + threadIdx.x;
    float4 v = x[i];
    ((uint2*)g_xh)[i] = make_uint2(pack_hi2(v.x, v.y), pack_hi2(v.z, v.w));
    ((uint2*)g_xl)[i] = make_uint2(pack_lo2(v.x, v.y), pack_lo2(v.z, v.w));
}

// W[k][n] fp32 -> T[n][k] bf16 hi/lo (k dim = 1024). WHICH 0: wqkv, 1: wout.
template<int WHICH>
__global__ __launch_bounds__(256) void conv_wT(const float* __restrict__ W) {
    __nv_bfloat16* Th = (WHICH == 0) ? g_wqh : g_woh;
    __nv_bfloat16* Tl = (WHICH == 0) ? g_wql : g_wol;
    const int N = (WHICH == 0) ? QKVN : DIM;
    __shared__ float t[32][33];
    const int tx = threadIdx.x, ty = threadIdx.y;   // 32, 8
    const int n0 = blockIdx.x * 32, k0 = blockIdx.y * 32;
#pragma unroll
    for (int i = 0; i < 4; ++i)
        t[ty + i * 8][tx] = W[(size_t)(k0 + ty + i * 8) * N + n0 + tx];
    __syncthreads();
#pragma unroll
    for (int i = 0; i < 4; ++i) {
        const float v = t[tx][ty + i * 8];
        const size_t o = (size_t)(n0 + ty + i * 8) * DIM + k0 + tx;
        Th[o] = bf_hi(v);
        Tl[o] = bf_lo(v);
    }
}

// ===========================================================================
// bf16x3 GEMM, pure bf16 cp.async path. Block 128x128, BK=32, 8 warps
// (4m x 2n), warp tile 32x64, double-buffered, 2 CTAs/SM.
// MODE 0: A=x(h/l), B=wqkv^T, scatter epilogue -> Q/K (rowmaj) + V^T, hi/lo
// MODE 1: A=g_O(h/l), B=wout^T, C = A@W + bias -> out fp32
// ===========================================================================
#define BK 32
#define NC (DIM / BK)            // 32
#define ROWH 40
#define TILE_B (128 * ROWH * 2)  // 10240
#define STAGE (4 * TILE_B)       // 40960
#define SMEMG (2 * STAGE)        // 81920

template<int MODE>
__global__ __launch_bounds__(256, 2) void mma_gemm(const float* __restrict__ bias,
                                                   float* __restrict__ Cout) {
    extern __shared__ char smem[];
    const uint32_t smem_base = smem_u32(smem);
    const __nv_bfloat16* Ahp = (MODE == 0) ? g_xh : g_Oh;
    const __nv_bfloat16* Alp = (MODE == 0) ? g_xl : g_Ol;
    const __nv_bfloat16* Bhp = (MODE == 0) ? g_wqh : g_woh;
    const __nv_bfloat16* Blp = (MODE == 0) ? g_wql : g_wol;

    const int tid = threadIdx.x;
    const int lane = tid & 31, w = tid >> 5;
    const int wm = w & 3, wn = w >> 2;
    const int bm = blockIdx.x * 128;
    const int bn = blockIdx.y * 128;

    const int a_row0 = wm * 32 + (lane & 15);
    const int a_colb = (lane >> 4) * 8;
    const int b_grp = lane >> 3, b_l8 = lane & 7;
    const int b_row0 = wn * 64 + ((b_grp >> 1) << 3) + b_l8;
    const int b_colb = (b_grp & 1) * 8;

    float acc[2][8][4];
#pragma unroll
    for (int i = 0; i < 2; ++i)
#pragma unroll
        for (int j = 0; j < 8; ++j)
#pragma unroll
            for (int k = 0; k < 4; ++k) acc[i][j][k] = 0.f;

#define GLOADC(st, c) do {                                                    \
    const uint32_t sB = smem_base + (st) * STAGE;                             \
    _Pragma("unroll")                                                         \
    for (int it = 0; it < 2; ++it) {                                          \
        const int id = tid + it * 256;                                        \
        const int r = id >> 2, q8 = (id & 3) * 8;                             \
        const uint32_t so = sB + (uint32_t)(r * ROWH + q8) * 2;               \
        const size_t ai = (size_t)(bm + r) * DIM + (c) * BK + q8;             \
        CP16(so,              (const char*)(Ahp + ai));                       \
        CP16(so + TILE_B,     (const char*)(Alp + ai));                       \
        const size_t bi = (size_t)(bn + r) * DIM + (c) * BK + q8;             \
        CP16(so + 2 * TILE_B, (const char*)(Bhp + bi));                       \
        CP16(so + 3 * TILE_B, (const char*)(Blp + bi));                       \
    }                                                                         \
    CPCOMMIT();                                                               \
} while (0)

    GLOADC(0, 0);
    GLOADC(1, 1);

    for (int c = 0; c < NC; ++c) {
        if (c + 1 < NC) { CPWAIT1(); } else { CPWAIT0(); }
        __syncthreads();

        const uint32_t base = smem_base + (c & 1) * STAGE;
#pragma unroll
        for (int ks = 0; ks < 2; ++ks) {
            uint32_t ah[2][4], al[2][4], bh[4][4], bl[4][4];
#pragma unroll
            for (int tm = 0; tm < 2; ++tm) {
                const uint32_t off =
                    ((a_row0 + tm * 16) * ROWH + ks * 16 + a_colb) * 2;
                ldsm4(ah[tm], base + off);
                ldsm4(al[tm], base + TILE_B + off);
            }
#pragma unroll
            for (int t2 = 0; t2 < 4; ++t2) {
                const uint32_t off =
                    ((b_row0 + t2 * 16) * ROWH + ks * 16 + b_colb) * 2;
                ldsm4(bh[t2], base + 2 * TILE_B + off);
                ldsm4(bl[t2], base + 3 * TILE_B + off);
            }
#pragma unroll
            for (int tm = 0; tm < 2; ++tm)
#pragma unroll
                for (int tn = 0; tn < 8; ++tn) {
                    const uint32_t* bhq = &bh[tn >> 1][(tn & 1) * 2];
                    const uint32_t* blq = &bl[tn >> 1][(tn & 1) * 2];
                    mma16816(acc[tm][tn], ah[tm], bhq);
                    mma16816(acc[tm][tn], ah[tm], blq);
                    mma16816(acc[tm][tn], al[tm], bhq);
                }
        }
        __syncthreads();
        if (c + 2 < NC) GLOADC(c & 1, c + 2);
    }

    const int r0 = bm + wm * 32 + (lane >> 2);
    const int c0b = wn * 64 + (lane & 3) * 2;
    if (MODE == 0) {
        const int sec = bn >> 10;
        const int innerb = (bn & 1023) + c0b;
#pragma unroll
        for (int tm = 0; tm < 2; ++tm)
#pragma unroll
            for (int tn = 0; tn < 8; ++tn) {
                const int inner = innerb + tn * 8;
                const int h = inner >> 6, d = inner & 63;
#pragma unroll
                for (int rr = 0; rr < 2; ++rr) {
                    const int mrow = r0 + tm * 16 + rr * 8;
                    const int bb = mrow >> 11, nn = mrow & (SEQ - 1);
                    float v0 = acc[tm][tn][rr * 2], v1 = acc[tm][tn][rr * 2 + 1];
                    const size_t bhh = (size_t)(bb * HEADS + h);
                    if (sec == 0) {
                        v0 *= 0.125f; v1 *= 0.125f;
                        const size_t ib = (bhh * SEQ + nn) * DH + d;
                        *(uint32_t*)&g_Qh[ib] = pack_hi2(v0, v1);
                        *(uint32_t*)&g_Ql[ib] = pack_lo2(v0, v1);
                    } else if (sec == 1) {
                        const size_t ib = (bhh * SEQ + nn) * DH + d;
                        *(uint32_t*)&g_Kh[ib] = pack_hi2(v0, v1);
                        *(uint32_t*)&g_Kl[ib] = pack_lo2(v0, v1);
                    } else {
                        const size_t tb = (bhh * DH + d) * SEQ + nn;
                        g_Vth[tb] = bf_hi(v0);       g_Vtl[tb] = bf_lo(v0);
                        g_Vth[tb + SEQ] = bf_hi(v1); g_Vtl[tb + SEQ] = bf_lo(v1);
                    }
                }
            }
    } else {
#pragma unroll
        for (int tm = 0; tm < 2; ++tm)
#pragma unroll
            for (int tn = 0; tn < 8; ++tn) {
                const int cc = bn + c0b + tn * 8;
                float2 bv = *(const float2*)(bias + cc);
#pragma unroll
                for (int rr = 0; rr < 2; ++rr) {
                    const int mrow = r0 + tm * 16 + rr * 8;
                    float* dst = Cout + (size_t)mrow * DIM + cc;
                    *(float2*)dst = make_float2(acc[tm][tn][rr * 2] + bv.x,
                                                acc[tm][tn][rr * 2 + 1] + bv.y);
                }
            }
    }
#undef GLOADC
}

// ===========================================================================
// Flash attention on mma.sync, bf16x3; epilogue writes bf16 hi/lo.
// ===========================================================================
#define ASTR 72
#define AQH 0
#define AQL 18432
#define ASTG 36864
#define ASTGSZ 36864
#define SMEM_FA (ASTG + 2 * ASTGSZ)   // 110592

__global__ __launch_bounds__(256) void flash_mma() {
    extern __shared__ char smf[];
    const uint32_t sb = smem_u32(smf);
    const int tid = threadIdx.x;
    const int lane = tid & 31, w = tid >> 5;
    const int bh = blockIdx.y;
    const int q0 = blockIdx.x * 128;

    {
        const size_t qb = ((size_t)bh * SEQ + q0) * DH;
#pragma unroll
        for (int it = 0; it < 4; ++it) {
            const int i = tid + it * 256;
            const int r = i >> 3, cc = i & 7;
            const uint32_t so = sb + (uint32_t)(r * ASTR + cc * 8) * 2;
            const size_t gi = qb + (size_t)r * DH + cc * 8;
            CP16(so + AQH, (const char*)(g_Qh + gi));
            CP16(so + AQL, (const char*)(g_Ql + gi));
        }
    }

#define LOADSTG(st, kv0) do {                                                 \
    _Pragma("unroll")                                                         \
    for (int it = 0; it < 2; ++it) {                                          \
        const int i = tid + it * 256;                                         \
        const int r = i >> 3, cc = i & 7;                                     \
        const uint32_t so = sb + ASTG + (st) * ASTGSZ +                       \
                            (uint32_t)(r * ASTR + cc * 8) * 2;                \
        const size_t ki = ((size_t)bh * SEQ + (kv0) + r) * DH + cc * 8;       \
        CP16(so,         (const char*)(g_Kh + ki));                           \
        CP16(so + 9216,  (const char*)(g_Kl + ki));                           \
        const size_t vi = ((size_t)bh * DH + r) * SEQ + (kv0) + cc * 8;       \
        CP16(so + 18432, (const char*)(g_Vth + vi));                          \
        CP16(so + 27648, (const char*)(g_Vtl + vi));                          \
    }                                                                         \
    CPCOMMIT();                                                               \
} while (0)

    LOADSTG(0, 0);

    const int a_row = w * 16 + (lane & 15);
    const uint32_t a_off = (uint32_t)(a_row * ASTR + (lane >> 4) * 8) * 2;
    const int b_grp = lane >> 3, b_l8 = lane & 7;
    const int b_row0 = ((b_grp >> 1) << 3) + b_l8;
    const int b_colb = (b_grp & 1) * 8;

    float m0 = -1e30f, m1 = -1e30f, l0 = 0.f, l1 = 0.f;
    float O[8][4];
#pragma unroll
    for (int j = 0; j < 8; ++j)
#pragma unroll
        for (int k = 0; k < 4; ++k) O[j][k] = 0.f;

    for (int c = 0; c < 32; ++c) {
        CPWAIT0();
        __syncthreads();
        if (c + 1 < 32) LOADSTG((c + 1) & 1, (c + 1) * 64);

        const uint32_t kb = sb + ASTG + (c & 1) * ASTGSZ;

        float S[8][4];
#pragma unroll
        for (int j = 0; j < 8; ++j)
#pragma unroll
            for (int k = 0; k < 4; ++k) S[j][k] = 0.f;
#pragma unroll
        for (int ks = 0; ks < 4; ++ks) {
            uint32_t ah[4], al[4];
            ldsm4(ah, sb + AQH + a_off + ks * 32);
            ldsm4(al, sb + AQL + a_off + ks * 32);
            uint32_t kh4[4][4], kl4[4][4];
#pragma unroll
            for (int t2 = 0; t2 < 4; ++t2) {
                const uint32_t off =
                    (uint32_t)((b_row0 + t2 * 16) * ASTR + ks * 16 + b_colb) * 2;
                ldsm4(kh4[t2], kb + off);
                ldsm4(kl4[t2], kb + 9216 + off);
            }
#pragma unroll
            for (int tn = 0; tn < 8; ++tn) {
                const uint32_t* bhq = &kh4[tn >> 1][(tn & 1) * 2];
                const uint32_t* blq = &kl4[tn >> 1][(tn & 1) * 2];
                mma16816(S[tn], ah, bhq);
                mma16816(S[tn], ah, blq);
                mma16816(S[tn], al, bhq);
            }
        }

        float mx0 = -1e30f, mx1 = -1e30f;
#pragma unroll
        for (int tn = 0; tn < 8; ++tn) {
            mx0 = fmaxf(mx0, fmaxf(S[tn][0], S[tn][1]));
            mx1 = fmaxf(mx1, fmaxf(S[tn][2], S[tn][3]));
        }
        mx0 = fmaxf(mx0, __shfl_xor_sync(0xffffffffu, mx0, 1));
        mx0 = fmaxf(mx0, __shfl_xor_sync(0xffffffffu, mx0, 2));
        mx1 = fmaxf(mx1, __shfl_xor_sync(0xffffffffu, mx1, 1));
        mx1 = fmaxf(mx1, __shfl_xor_sync(0xffffffffu, mx1, 2));
        const float mn0 = fmaxf(m0, mx0), mn1 = fmaxf(m1, mx1);
        float s0 = 0.f, s1 = 0.f;
#pragma unroll
        for (int tn = 0; tn < 8; ++tn) {
            S[tn][0] = __expf(S[tn][0] - mn0); s0 += S[tn][0];
            S[tn][1] = __expf(S[tn][1] - mn0); s0 += S[tn][1];
            S[tn][2] = __expf(S[tn][2] - mn1); s1 += S[tn][2];
            S[tn][3] = __expf(S[tn][3] - mn1); s1 += S[tn][3];
        }
        s0 += __shfl_xor_sync(0xffffffffu, s0, 1);
        s0 += __shfl_xor_sync(0xffffffffu, s0, 2);
        s1 += __shfl_xor_sync(0xffffffffu, s1, 1);
        s1 += __shfl_xor_sync(0xffffffffu, s1, 2);
        const float al0 = __expf(m0 - mn0), al1 = __expf(m1 - mn1);
        m0 = mn0; m1 = mn1;
        l0 = l0 * al0 + s0;
        l1 = l1 * al1 + s1;
#pragma unroll
        for (int tn = 0; tn < 8; ++tn) {
            O[tn][0] *= al0; O[tn][1] *= al0;
            O[tn][2] *= al1; O[tn][3] *= al1;
        }

        uint32_t pa[4][4], pl[4][4];
#pragma unroll
        for (int ks = 0; ks < 4; ++ks) {
            pa[ks][0] = pack_hi2(S[2*ks][0],   S[2*ks][1]);
            pa[ks][1] = pack_hi2(S[2*ks][2],   S[2*ks][3]);
            pa[ks][2] = pack_hi2(S[2*ks+1][0], S[2*ks+1][1]);
            pa[ks][3] = pack_hi2(S[2*ks+1][2], S[2*ks+1][3]);
            pl[ks][0] = pack_lo2(S[2*ks][0],   S[2*ks][1]);
            pl[ks][1] = pack_lo2(S[2*ks][2],   S[2*ks][3]);
            pl[ks][2] = pack_lo2(S[2*ks+1][0], S[2*ks+1][1]);
            pl[ks][3] = pack_lo2(S[2*ks+1][2], S[2*ks+1][3]);
        }

#pragma unroll
        for (int ks = 0; ks < 4; ++ks) {
            uint32_t vh4[4][4], vl4[4][4];
#pragma unroll
            for (int t2 = 0; t2 < 4; ++t2) {
                const uint32_t off =
                    (uint32_t)((b_row0 + t2 * 16) * ASTR + ks * 16 + b_colb) * 2;
                ldsm4(vh4[t2], kb + 18432 + off);
                ldsm4(vl4[t2], kb + 27648 + off);
            }
#pragma unroll
            for (int tn = 0; tn < 8; ++tn) {
                const uint32_t* bhq = &vh4[tn >> 1][(tn & 1) * 2];
                const uint32_t* blq = &vl4[tn >> 1][(tn & 1) * 2];
                mma16816(O[tn], pa[ks], bhq);
                mma16816(O[tn], pa[ks], blq);
                mma16816(O[tn], pl[ks], bhq);
            }
        }
    }

    const int bb = bh >> 4, hh = bh & 15;
    const float inv0 = 1.f / l0, inv1 = 1.f / l1;
    const int r0g = q0 + w * 16 + (lane >> 2);
    const int cb = hh * 64 + (lane & 3) * 2;
#pragma unroll
    for (int tn = 0; tn < 8; ++tn) {
        const size_t i0 = ((size_t)(bb * SEQ + r0g) * DIM + cb + tn * 8);
        const float a0 = O[tn][0] * inv0, a1 = O[tn][1] * inv0;
        *(uint32_t*)&g_Oh[i0] = pack_hi2(a0, a1);
        *(uint32_t*)&g_Ol[i0] = pack_lo2(a0, a1);
        const size_t i1 = ((size_t)(bb * SEQ + r0g + 8) * DIM + cb + tn * 8);
        const float c0 = O[tn][2] * inv1, c1 = O[tn][3] * inv1;
        *(uint32_t*)&g_Oh[i1] = pack_hi2(c0, c1);
        *(uint32_t*)&g_Ol[i1] = pack_lo2(c0, c1);
    }
#undef LOADSTG
}

extern "C" void kernel_launch(void* const* d_in, const int* in_sizes, int n_in,
                              void* d_out, int out_size) {
    const float* x     = (const float*)d_in[0];
    const float* w_qkv = (const float*)d_in[1];
    const float* w_out = (const float*)d_in[2];
    const float* b_out = (const float*)d_in[3];
    float* out = (float*)d_out;

    cudaFuncSetAttribute(mma_gemm<0>, cudaFuncAttributeMaxDynamicSharedMemorySize,
                         SMEMG);
    cudaFuncSetAttribute(mma_gemm<1>, cudaFuncAttributeMaxDynamicSharedMemorySize,
                         SMEMG);
    cudaFuncSetAttribute(flash_mma, cudaFuncAttributeMaxDynamicSharedMemorySize,
                         SMEM_FA);

    // prep: fp32 -> bf16 hi/lo (+ weight transpose); destinations are
    // device globals referenced inside the kernels (no symbol ptrs from host)
    conv_x<<<MTOT * DIM / 4 / 256, 256>>>((const float4*)x);
    conv_wT<0><<<dim3(QKVN / 32, DIM / 32), dim3(32, 8)>>>(w_qkv);
    conv_wT<1><<<dim3(DIM / 32, DIM / 32), dim3(32, 8)>>>(w_out);

    mma_gemm<0><<<dim3(MTOT / 128, QKVN / 128), 256, SMEMG>>>(nullptr, nullptr);
    flash_mma<<<dim3(SEQ / 128, BATCH * HEADS), 256, SMEM_FA>>>();
    mma_gemm<1><<<dim3(MTOT / 128, DIM / 128), 256, SMEMG>>>(b_out, out);
}